// round 3
// baseline (speedup 1.0000x reference)
#include <cuda_runtime.h>
#include <math.h>

#define B      4096
#define NSUB   20
#define NNEG   5
#define DIM    128
#define EPB    4                        // batch elements per block
#define GRID   (B / EPB)                // 1024 blocks
#define NTHR   256                      // 8 warps: 2 per element (DIM split)

__device__ float    g_partial[GRID];
__device__ unsigned g_done = 0;

__device__ __forceinline__ float log_sigmoid_f(float x) {
    return fminf(x, 0.0f) - log1pf(expf(-fabsf(x)));
}

__global__ __launch_bounds__(NTHR, 6)
void fasttext_fused_kernel(const int* __restrict__ u_pos,
                           const int* __restrict__ v_pos,
                           const int* __restrict__ v_neg,
                           const float* __restrict__ uw,
                           const float* __restrict__ vw,
                           float* __restrict__ out) {
    const int lane = threadIdx.x & 31;
    const int warp = threadIdx.x >> 5;
    const int pair = warp >> 1;                    // element slot within block
    const int half = warp & 1;                     // which 64-dim half
    const int b    = blockIdx.x * EPB + pair;

    // float2 view: row stride = 64 float2; this warp covers float2 [half*32+lane]
    const int d2 = half * 32 + lane;
    const float2* uw2 = (const float2*)uw;
    const float2* vw2 = (const float2*)vw;

    // ---- stage indices into registers (lane-strided), broadcast via shfl ----
    int iu = 0, iv = 0;
    if (lane < NSUB) {
        iu = u_pos[b * NSUB + lane];
        iv = v_pos[b * NSUB + lane];
    }
    int in0, in1, in2, in3 = 0;
    {
        const int base = b * NSUB * NNEG;
        in0 = v_neg[base + lane];
        in1 = v_neg[base + 32 + lane];
        in2 = v_neg[base + 64 + lane];
        if (lane < 4) in3 = v_neg[base + 96 + lane];
    }

    // ---- gather + accumulate over this warp's 64 dims ----
    float2 ua = make_float2(0.f, 0.f);
    float2 va = make_float2(0.f, 0.f);

    #pragma unroll
    for (int s = 0; s < NSUB; ++s) {
        const int idx_u = __shfl_sync(0xFFFFFFFFu, iu, s);
        const int idx_v = __shfl_sync(0xFFFFFFFFu, iv, s);
        if (idx_u != 0) {                              // padding_idx = 0
            float2 r = uw2[(long)idx_u * 64 + d2];
            ua.x += r.x; ua.y += r.y;
        }
        float2 r = vw2[(long)idx_v * 64 + d2];
        va.x += r.x; va.y += r.y;
    }

    float2 na[NNEG];
    #pragma unroll
    for (int n = 0; n < NNEG; ++n) na[n] = make_float2(0.f, 0.f);

    // layout [NSUB, NNEG]: j = s*NNEG + n  ->  accumulator n = j % NNEG
    #pragma unroll
    for (int j = 0; j < NSUB * NNEG; ++j) {
        int src;
        if      (j < 32) src = __shfl_sync(0xFFFFFFFFu, in0, j);
        else if (j < 64) src = __shfl_sync(0xFFFFFFFFu, in1, j - 32);
        else if (j < 96) src = __shfl_sync(0xFFFFFFFFu, in2, j - 64);
        else             src = __shfl_sync(0xFFFFFFFFu, in3, j - 96);
        float2 r = vw2[(long)src * 64 + d2];
        const int n = j % NNEG;
        na[n].x += r.x; na[n].y += r.y;
    }

    // ---- six partial dots over this warp's 64 dims, warp-reduced ----
    float p[1 + NNEG];
    p[0] = ua.x * va.x + ua.y * va.y;
    #pragma unroll
    for (int n = 0; n < NNEG; ++n)
        p[1 + n] = ua.x * na[n].x + ua.y * na[n].y;

    #pragma unroll
    for (int i = 0; i < 1 + NNEG; ++i) {
        #pragma unroll
        for (int off = 16; off > 0; off >>= 1)
            p[i] += __shfl_xor_sync(0xFFFFFFFFu, p[i], off);
    }

    // ---- combine the two DIM-halves, compute per-element loss ----
    __shared__ float s_dot[EPB][2][1 + NNEG];
    if (lane == 0) {
        #pragma unroll
        for (int i = 0; i < 1 + NNEG; ++i) s_dot[pair][half][i] = p[i];
    }
    __syncthreads();

    __shared__ float s_loss[EPB];
    if (half == 0 && lane == 0) {
        const float inv_ns2 = 1.0f / (float)(NSUB * NSUB);
        float score = (s_dot[pair][0][0] + s_dot[pair][1][0]) * inv_ns2;
        float loss = log_sigmoid_f(score);
        #pragma unroll
        for (int n = 0; n < NNEG; ++n) {
            float ns = (s_dot[pair][0][1 + n] + s_dot[pair][1][1 + n]) * inv_ns2;
            loss += log_sigmoid_f(-ns);
        }
        s_loss[pair] = loss;
    }
    __syncthreads();

    // ---- per-block partial, then last-block deterministic final reduce ----
    __shared__ bool s_last;
    if (threadIdx.x == 0) {
        g_partial[blockIdx.x] = s_loss[0] + s_loss[1] + s_loss[2] + s_loss[3];
        __threadfence();
        unsigned prev = atomicAdd(&g_done, 1u);
        s_last = (prev == GRID - 1);
    }
    __syncthreads();

    if (s_last) {
        __threadfence();
        const int t = threadIdx.x;                 // 256 threads
        float a = 0.0f;
        #pragma unroll
        for (int k = 0; k < GRID / NTHR; ++k)      // fixed order: deterministic
            a += *((volatile float*)&g_partial[t + k * NTHR]);
        __shared__ float red[NTHR];
        red[t] = a;
        __syncthreads();
        #pragma unroll
        for (int off = NTHR / 2; off > 0; off >>= 1) {
            if (t < off) red[t] += red[t + off];
            __syncthreads();
        }
        if (t == 0) {
            out[0] = -red[0] / (float)B;
            g_done = 0;                            // reset for next graph replay
        }
    }
}

extern "C" void kernel_launch(void* const* d_in, const int* in_sizes, int n_in,
                              void* d_out, int out_size) {
    // metadata order: u_pos, v_pos, v_neg, batch_size, u_weight, v_weight
    const int*   u_pos = (const int*)d_in[0];
    const int*   v_pos = (const int*)d_in[1];
    const int*   v_neg = (const int*)d_in[2];
    const float* uw    = (const float*)d_in[4];
    const float* vw    = (const float*)d_in[5];
    float* out = (float*)d_out;

    fasttext_fused_kernel<<<GRID, NTHR>>>(u_pos, v_pos, v_neg, uw, vw, out);
}

// round 4
// speedup vs baseline: 1.0084x; 1.0084x over previous
#include <cuda_runtime.h>
#include <math.h>

#define B      4096
#define NSUB   20
#define NNEG   5
#define DIM    128
#define EPB    4                        // batch elements per block
#define GRID   (B / EPB)                // 1024 blocks
#define NTHR   256                      // 8 warps: 2 per element (row split)
#define HSUB   (NSUB / 2)               // 10 u/v rows per warp
#define HNEG   (NSUB * NNEG / 2)        // 50 neg rows per warp

__device__ float    g_partial[GRID];
__device__ unsigned g_done = 0;

__device__ __forceinline__ float log_sigmoid_f(float x) {
    return fminf(x, 0.0f) - log1pf(expf(-fabsf(x)));
}

__global__ __launch_bounds__(NTHR, 6)
void fasttext_fused_kernel(const int* __restrict__ u_pos,
                           const int* __restrict__ v_pos,
                           const int* __restrict__ v_neg,
                           const float* __restrict__ uw,
                           const float* __restrict__ vw,
                           float* __restrict__ out) {
    const int lane = threadIdx.x & 31;
    const int warp = threadIdx.x >> 5;
    const int pair = warp >> 1;                    // element slot in block
    const int half = warp & 1;                     // which half of the rows
    const int b    = blockIdx.x * EPB + pair;

    const float4* uw4 = (const float4*)uw;         // row stride = 32 float4
    const float4* vw4 = (const float4*)vw;

    // ---- stage this warp's indices into registers ----
    int iu = 0, iv = 0;
    if (lane < HSUB) {
        iu = u_pos[b * NSUB + half * HSUB + lane];
        iv = v_pos[b * NSUB + half * HSUB + lane];
    }
    int in0, in1 = 0;
    {
        const int base = b * NSUB * NNEG + half * HNEG;
        in0 = v_neg[base + lane];
        if (lane < HNEG - 32) in1 = v_neg[base + 32 + lane];
    }

    // ---- phase 1: partial embed_u / embed_v over this warp's 10 rows ----
    float4 ua = make_float4(0.f, 0.f, 0.f, 0.f);
    float4 va = make_float4(0.f, 0.f, 0.f, 0.f);

    #pragma unroll
    for (int s = 0; s < HSUB; ++s) {
        const int idx_u = __shfl_sync(0xFFFFFFFFu, iu, s);
        const int idx_v = __shfl_sync(0xFFFFFFFFu, iv, s);
        if (idx_u != 0) {                              // padding_idx = 0
            float4 r = uw4[(long)idx_u * 32 + lane];
            ua.x += r.x; ua.y += r.y; ua.z += r.z; ua.w += r.w;
        }
        float4 r = vw4[(long)idx_v * 32 + lane];
        va.x += r.x; va.y += r.y; va.z += r.z; va.w += r.w;
    }

    // ---- exchange partial ua between the two warps -> full embed_u ----
    __shared__ float4 s_ua[EPB][2][32];
    s_ua[pair][half][lane] = ua;
    __syncthreads();
    {
        float4 o = s_ua[pair][half ^ 1][lane];
        ua.x += o.x; ua.y += o.y; ua.z += o.z; ua.w += o.w;
    }

    // pos-score partial: dot(full ua, partial va)
    float p0 = ua.x * va.x + ua.y * va.y + ua.z * va.z + ua.w * va.w;

    // ---- phase 2: neg rows fold directly into scalar dots with full ua ----
    float nacc[NNEG];
    #pragma unroll
    for (int n = 0; n < NNEG; ++n) nacc[n] = 0.0f;

    // global j = half*HNEG + j'; n = j % 5 = j' % 5 (HNEG % 5 == 0)
    #pragma unroll
    for (int j = 0; j < HNEG; ++j) {
        const int src = (j < 32) ? __shfl_sync(0xFFFFFFFFu, in0, j)
                                 : __shfl_sync(0xFFFFFFFFu, in1, j - 32);
        float4 r = vw4[(long)src * 32 + lane];
        const int n = j % NNEG;
        nacc[n] += r.x * ua.x + r.y * ua.y + r.z * ua.z + r.w * ua.w;
    }

    // ---- warp-reduce the 6 scalars ----
    float p[1 + NNEG];
    p[0] = p0;
    #pragma unroll
    for (int n = 0; n < NNEG; ++n) p[1 + n] = nacc[n];
    #pragma unroll
    for (int i = 0; i < 1 + NNEG; ++i) {
        #pragma unroll
        for (int off = 16; off > 0; off >>= 1)
            p[i] += __shfl_xor_sync(0xFFFFFFFFu, p[i], off);
    }

    // ---- combine the two row-halves, per-element loss ----
    __shared__ float s_dot[EPB][2][1 + NNEG];
    if (lane == 0) {
        #pragma unroll
        for (int i = 0; i < 1 + NNEG; ++i) s_dot[pair][half][i] = p[i];
    }
    __syncthreads();

    __shared__ float s_loss[EPB];
    if (half == 0 && lane == 0) {
        const float inv_ns2 = 1.0f / (float)(NSUB * NSUB);
        float score = (s_dot[pair][0][0] + s_dot[pair][1][0]) * inv_ns2;
        float loss = log_sigmoid_f(score);
        #pragma unroll
        for (int n = 0; n < NNEG; ++n) {
            float ns = (s_dot[pair][0][1 + n] + s_dot[pair][1][1 + n]) * inv_ns2;
            loss += log_sigmoid_f(-ns);
        }
        s_loss[pair] = loss;
    }
    __syncthreads();

    // ---- per-block partial, last-block deterministic final reduce ----
    __shared__ bool s_last;
    if (threadIdx.x == 0) {
        g_partial[blockIdx.x] = s_loss[0] + s_loss[1] + s_loss[2] + s_loss[3];
        __threadfence();
        unsigned prev = atomicAdd(&g_done, 1u);
        s_last = (prev == GRID - 1);
    }
    __syncthreads();

    if (s_last) {
        __threadfence();
        const int t = threadIdx.x;                 // 256 threads
        float a = 0.0f;
        #pragma unroll
        for (int k = 0; k < GRID / NTHR; ++k)      // fixed order: deterministic
            a += *((volatile float*)&g_partial[t + k * NTHR]);
        __shared__ float red[NTHR];
        red[t] = a;
        __syncthreads();
        #pragma unroll
        for (int off = NTHR / 2; off > 0; off >>= 1) {
            if (t < off) red[t] += red[t + off];
            __syncthreads();
        }
        if (t == 0) {
            out[0] = -red[0] / (float)B;
            g_done = 0;                            // reset for next graph replay
        }
    }
}

extern "C" void kernel_launch(void* const* d_in, const int* in_sizes, int n_in,
                              void* d_out, int out_size) {
    // metadata order: u_pos, v_pos, v_neg, batch_size, u_weight, v_weight
    const int*   u_pos = (const int*)d_in[0];
    const int*   v_pos = (const int*)d_in[1];
    const int*   v_neg = (const int*)d_in[2];
    const float* uw    = (const float*)d_in[4];
    const float* vw    = (const float*)d_in[5];
    float* out = (float*)d_out;

    fasttext_fused_kernel<<<GRID, NTHR>>>(u_pos, v_pos, v_neg, uw, vw, out);
}

// round 5
// speedup vs baseline: 1.0345x; 1.0259x over previous
#include <cuda_runtime.h>
#include <math.h>

#define B      4096
#define NSUB   20
#define NNEG   5
#define DIM    128
#define EPB    2                        // batch elements per block
#define GRID   (B / EPB)                // 2048 blocks
#define NTHR   128                      // 4 warps: 2 per element (row split)
#define HSUB   (NSUB / 2)               // 10 u/v rows per warp
#define HNEG   (NSUB * NNEG / 2)        // 50 neg rows per warp
#define NVEC   (2 + NNEG)               // ua, va, na[5]

__device__ float    g_partial[GRID];
__device__ unsigned g_done = 0;

__device__ __forceinline__ float log_sigmoid_f(float x) {
    return fminf(x, 0.0f) - log1pf(expf(-fabsf(x)));
}

__global__ __launch_bounds__(NTHR)
void fasttext_fused_kernel(const int* __restrict__ u_pos,
                           const int* __restrict__ v_pos,
                           const int* __restrict__ v_neg,
                           const float* __restrict__ uw,
                           const float* __restrict__ vw,
                           float* __restrict__ out) {
    const int lane = threadIdx.x & 31;
    const int warp = threadIdx.x >> 5;
    const int pair = warp >> 1;                    // element slot in block
    const int half = warp & 1;                     // which half of the rows
    const int b    = blockIdx.x * EPB + pair;

    const float4* uw4 = (const float4*)uw;         // row stride = 32 float4
    const float4* vw4 = (const float4*)vw;

    // ---- stage this warp's indices into lane registers ----
    int iu = 0, iv = 0;
    if (lane < HSUB) {
        iu = u_pos[b * NSUB + half * HSUB + lane];
        iv = v_pos[b * NSUB + half * HSUB + lane];
    }
    int in0, in1 = 0;
    {
        const int base = b * NSUB * NNEG + half * HNEG;
        in0 = v_neg[base + lane];
        if (lane < HNEG - 32) in1 = v_neg[base + 32 + lane];
    }

    // ---- all gathers: independent accumulators, NO barriers anywhere ----
    float4 acc[NVEC];                               // 0=ua 1=va 2..6=na
    #pragma unroll
    for (int i = 0; i < NVEC; ++i) acc[i] = make_float4(0.f, 0.f, 0.f, 0.f);

    #pragma unroll
    for (int s = 0; s < HSUB; ++s) {
        const int idx_u = __shfl_sync(0xFFFFFFFFu, iu, s);
        const int idx_v = __shfl_sync(0xFFFFFFFFu, iv, s);
        if (idx_u != 0) {                           // padding_idx = 0
            float4 r = uw4[(long)idx_u * 32 + lane];
            acc[0].x += r.x; acc[0].y += r.y; acc[0].z += r.z; acc[0].w += r.w;
        }
        float4 r = vw4[(long)idx_v * 32 + lane];
        acc[1].x += r.x; acc[1].y += r.y; acc[1].z += r.z; acc[1].w += r.w;
    }

    // global j = half*HNEG + j'; n = j % 5 = j' % 5  (HNEG % 5 == 0)
    #pragma unroll
    for (int j = 0; j < HNEG; ++j) {
        const int src = (j < 32) ? __shfl_sync(0xFFFFFFFFu, in0, j)
                                 : __shfl_sync(0xFFFFFFFFu, in1, j - 32);
        float4 r = vw4[(long)src * 32 + lane];
        const int n = 2 + (j % NNEG);
        acc[n].x += r.x; acc[n].y += r.y; acc[n].z += r.z; acc[n].w += r.w;
    }

    // ---- single barrier: exchange partial vectors via smem ----
    __shared__ float4 s_vec[EPB][2][NVEC][32];
    #pragma unroll
    for (int i = 0; i < NVEC; ++i) s_vec[pair][half][i][lane] = acc[i];
    __syncthreads();

    __shared__ float s_loss[EPB];
    if (half == 0) {
        // combine both halves -> full embed vectors (this lane's 4 dims)
        float4 v[NVEC];
        #pragma unroll
        for (int i = 0; i < NVEC; ++i) {
            float4 a = s_vec[pair][0][i][lane];
            float4 c = s_vec[pair][1][i][lane];
            v[i] = make_float4(a.x + c.x, a.y + c.y, a.z + c.z, a.w + c.w);
        }
        // six dots vs full embed_u
        float p[1 + NNEG];
        #pragma unroll
        for (int i = 0; i < 1 + NNEG; ++i) {
            const float4 w = v[1 + i];              // va or na[n]
            p[i] = v[0].x * w.x + v[0].y * w.y + v[0].z * w.z + v[0].w * w.w;
            #pragma unroll
            for (int off = 16; off > 0; off >>= 1)
                p[i] += __shfl_xor_sync(0xFFFFFFFFu, p[i], off);
        }
        if (lane == 0) {
            const float inv_ns2 = 1.0f / (float)(NSUB * NSUB);
            float loss = log_sigmoid_f(p[0] * inv_ns2);
            #pragma unroll
            for (int n = 0; n < NNEG; ++n)
                loss += log_sigmoid_f(-(p[1 + n] * inv_ns2));
            s_loss[pair] = loss;
        }
    }
    __syncthreads();

    // ---- per-block partial, last-block deterministic final reduce ----
    __shared__ bool s_last;
    if (threadIdx.x == 0) {
        g_partial[blockIdx.x] = s_loss[0] + s_loss[1];
        __threadfence();
        unsigned prev = atomicAdd(&g_done, 1u);
        s_last = (prev == GRID - 1);
    }
    __syncthreads();

    if (s_last) {
        __threadfence();
        const int t = threadIdx.x;                  // 128 threads
        float a = 0.0f;
        #pragma unroll
        for (int k = 0; k < GRID / NTHR; ++k)       // fixed order: deterministic
            a += *((volatile float*)&g_partial[t + k * NTHR]);
        __shared__ float red[NTHR];
        red[t] = a;
        __syncthreads();
        #pragma unroll
        for (int off = NTHR / 2; off > 0; off >>= 1) {
            if (t < off) red[t] += red[t + off];
            __syncthreads();
        }
        if (t == 0) {
            out[0] = -red[0] / (float)B;
            g_done = 0;                             // reset for next graph replay
        }
    }
}

extern "C" void kernel_launch(void* const* d_in, const int* in_sizes, int n_in,
                              void* d_out, int out_size) {
    // metadata order: u_pos, v_pos, v_neg, batch_size, u_weight, v_weight
    const int*   u_pos = (const int*)d_in[0];
    const int*   v_pos = (const int*)d_in[1];
    const int*   v_neg = (const int*)d_in[2];
    const float* uw    = (const float*)d_in[4];
    const float* vw    = (const float*)d_in[5];
    float* out = (float*)d_out;

    fasttext_fused_kernel<<<GRID, NTHR>>>(u_pos, v_pos, v_neg, uw, vw, out);
}